// round 1
// baseline (speedup 1.0000x reference)
#include <cuda_runtime.h>
#include <math.h>
#include <stdint.h>
#include <stddef.h>

#define TT 64
#define BB 512
#define FF 72
#define FP 96      // padded F (multiple of KC)
#define HH 1024
#define G4 4096
#define KC 32      // K chunk
#define SS 36      // smem row stride (floats): 16B-aligned, conflict-free
#define SMEM_BYTES (4 * (4 * 128 * SS))   // A[2][128][SS] + B[2][128][SS] = 73728 B

// ---------------------------------------------------------------------------
// Scratch (device globals; no allocations allowed)
// ---------------------------------------------------------------------------
struct __align__(16) Scratch {
    float xnf[TT * BB * FF];          // normalized input, f32 (for feedback gather)
    float xg[(TT - 1) * BB * FP];     // normalized+TF32-rounded, padded (enc GEMM A)
    float Wih0p[G4 * FP];             // TF32-rounded, zero-padded
    float Whh0c[G4 * HH];             // TF32-rounded
    float Wih1c[G4 * HH];
    float Whh1c[G4 * HH];
    float bias0[G4];                  // b_ih0 + b_hh0
    float bias1[G4];
    float h0[2][BB * HH];             // ping-pong, TF32-rounded values
    float h1[2][BB * HH];
    float c0[BB * HH];                // full f32
    float c1[BB * HH];
    float h0n[BB * HH];               // layer0 fresh output (TF32-rounded)
    float fb[BB * FF];                // feedback accumulator, full f32
    float fbt[BB * FP];               // TF32-rounded, padded (dec GEMM A)
};
__device__ Scratch g_scratch;

// ---------------------------------------------------------------------------
// Helpers
// ---------------------------------------------------------------------------
__device__ __forceinline__ float rna_tf32(float x) {
    uint32_t u;
    asm("cvt.rna.tf32.f32 %0, %1;" : "=r"(u) : "f"(x));
    return __uint_as_float(u);
}
__device__ __forceinline__ float sigmoidf_(float x) {
    return 1.0f / (1.0f + expf(-x));
}
__device__ __forceinline__ void cp16(uint32_t saddr, const void* gaddr) {
    asm volatile("cp.async.cg.shared.global [%0], [%1], 16;\n" :: "r"(saddr), "l"(gaddr));
}
__device__ __forceinline__ void mma_tf32(float* c, const uint32_t* a, const uint32_t* b) {
    asm volatile(
        "mma.sync.aligned.m16n8k8.row.col.f32.tf32.tf32.f32 "
        "{%0,%1,%2,%3},{%4,%5,%6,%7},{%8,%9},{%0,%1,%2,%3};\n"
        : "+f"(c[0]), "+f"(c[1]), "+f"(c[2]), "+f"(c[3])
        : "r"(a[0]), "r"(a[1]), "r"(a[2]), "r"(a[3]), "r"(b[0]), "r"(b[1]));
}

// ---------------------------------------------------------------------------
// Setup kernels
// ---------------------------------------------------------------------------
__global__ void norm_kernel(const float* __restrict__ u, const float* __restrict__ mean,
                            const float* __restrict__ stdv, float* __restrict__ xnf,
                            float* __restrict__ xg) {
    int idx = blockIdx.x * blockDim.x + threadIdx.x;
    if (idx >= TT * BB * FP) return;
    int j = idx % FP;
    int tb = idx / FP;
    int t = tb / BB, b = tb % BB;
    if (j < FF) {
        float v = (u[(t * BB + b) * FF + j] - mean[j]) / stdv[j];
        xnf[(t * BB + b) * FF + j] = v;
        if (t < TT - 1) xg[(t * BB + b) * FP + j] = rna_tf32(v);
    } else {
        if (t < TT - 1) xg[(t * BB + b) * FP + j] = 0.0f;
    }
}

__global__ void conv_kernel(const float* __restrict__ src, float* __restrict__ dst, int n) {
    int idx = blockIdx.x * blockDim.x + threadIdx.x;
    if (idx < n) dst[idx] = rna_tf32(src[idx]);
}

__global__ void pad_kernel(const float* __restrict__ src, float* __restrict__ dst) {
    int idx = blockIdx.x * blockDim.x + threadIdx.x;
    if (idx >= G4 * FP) return;
    int n = idx / FP, j = idx % FP;
    dst[idx] = (j < FF) ? rna_tf32(src[n * FF + j]) : 0.0f;
}

__global__ void bias_kernel(const float* bi0, const float* bh0, const float* bi1,
                            const float* bh1, float* b0, float* b1) {
    int idx = blockIdx.x * blockDim.x + threadIdx.x;
    if (idx < G4) {
        b0[idx] = bi0[idx] + bh0[idx];
        b1[idx] = bi1[idx] + bh1[idx];
    }
}

__global__ void gather_kernel(const int* __restrict__ lengths, const float* __restrict__ xnf,
                              float* __restrict__ fb, float* __restrict__ fbt) {
    int b = blockIdx.x, j = threadIdx.x;
    if (j >= FF) return;
    int tt = lengths[b] - 1;
    float v = xnf[(tt * BB + b) * FF + j];
    fb[b * FF + j] = v;
    fbt[b * FP + j] = rna_tf32(v);
}

// ---------------------------------------------------------------------------
// Fused GEMM + LSTM-cell epilogue.
// gates[m][n] = bias[n] + sum_k A0[m][k]*B0[n][k] + sum_k A1[m][k]*B1[n][k]
// CTA tile: 128 batch rows x 32 h-units x 4 gates (N=128).
// ---------------------------------------------------------------------------
__global__ void __launch_bounds__(256) lstm_gemm_kernel(
    const float* __restrict__ A0, int lda0, const float* __restrict__ B0, int ldb0, int K0,
    const float* __restrict__ A1, const float* __restrict__ B1, int K1,
    const float* __restrict__ bias,
    const float* __restrict__ h_read, float* __restrict__ h_write,
    float* __restrict__ cbuf, float* __restrict__ hn_out,
    const int* __restrict__ lengths, int t, int masked) {
    extern __shared__ float sm[];
    const int tid = threadIdx.x;
    const int lane = tid & 31, warp = tid >> 5;
    const int wm = warp & 3, wn = warp >> 2;       // 4 M-warps x 2 N-warps
    const int grp = lane >> 2, tig = lane & 3;
    const int m0 = blockIdx.x * 128;
    const int u0 = blockIdx.y * 32;
    const int C0 = K0 / KC;
    const int C = C0 + K1 / KC;
    const int ABUF = 128 * SS;                     // floats per buffer
    float* As = sm;                                // [2][128][SS]
    float* Bs = sm + 2 * ABUF;                     // [2][128][SS]
    const uint32_t sA = (uint32_t)__cvta_generic_to_shared(As);
    const uint32_t sB = (uint32_t)__cvta_generic_to_shared(Bs);

    float acc[2][8][4];
#pragma unroll
    for (int a = 0; a < 2; a++)
#pragma unroll
        for (int b = 0; b < 8; b++)
#pragma unroll
            for (int c = 0; c < 4; c++) acc[a][b][c] = 0.0f;

    auto issue = [&](int i, int s) {
        const float* Ag;
        const float* Bg;
        int la, lb, k0;
        if (i < C0) { Ag = A0; Bg = B0; la = lda0; lb = ldb0; k0 = i * KC; }
        else        { Ag = A1; Bg = B1; la = HH;   lb = HH;   k0 = (i - C0) * KC; }
#pragma unroll
        for (int r = 0; r < 4; r++) {
            int q = tid + 256 * r;
            int row = q >> 3, c4 = (q & 7) * 4;
            cp16(sA + 4 * (s * ABUF + row * SS + c4),
                 Ag + (size_t)(m0 + row) * la + k0 + c4);
        }
#pragma unroll
        for (int r = 0; r < 4; r++) {
            int q = tid + 256 * r;
            int row = q >> 3, c4 = (q & 7) * 4;
            int n = ((row >> 5) << 10) + u0 + (row & 31);   // gate*1024 + u0 + rr
            cp16(sB + 4 * (s * ABUF + row * SS + c4),
                 Bg + (size_t)n * lb + k0 + c4);
        }
        asm volatile("cp.async.commit_group;\n" ::);
    };

    issue(0, 0);
    for (int i = 0; i < C; i++) {
        int s = i & 1;
        if (i + 1 < C) {
            issue(i + 1, s ^ 1);
            asm volatile("cp.async.wait_group 1;\n" ::);
        } else {
            asm volatile("cp.async.wait_group 0;\n" ::);
        }
        __syncthreads();
        const float* Ab = As + s * ABUF;
        const float* Bb = Bs + s * ABUF;
#pragma unroll
        for (int ks = 0; ks < 4; ks++) {
            int kk = ks * 8;
            uint32_t bfr[8][2];
#pragma unroll
            for (int nb = 0; nb < 8; nb++) {
                int n = wn * 64 + nb * 8 + grp;
                bfr[nb][0] = __float_as_uint(Bb[n * SS + kk + tig]);
                bfr[nb][1] = __float_as_uint(Bb[n * SS + kk + tig + 4]);
            }
            uint32_t afr[2][4];
#pragma unroll
            for (int mb = 0; mb < 2; mb++) {
                int r0 = wm * 32 + mb * 16;
                afr[mb][0] = __float_as_uint(Ab[(r0 + grp) * SS + kk + tig]);
                afr[mb][1] = __float_as_uint(Ab[(r0 + 8 + grp) * SS + kk + tig]);
                afr[mb][2] = __float_as_uint(Ab[(r0 + grp) * SS + kk + tig + 4]);
                afr[mb][3] = __float_as_uint(Ab[(r0 + 8 + grp) * SS + kk + tig + 4]);
            }
#pragma unroll
            for (int mb = 0; mb < 2; mb++)
#pragma unroll
                for (int nb = 0; nb < 8; nb++) mma_tf32(acc[mb][nb], afr[mb], bfr[nb]);
        }
        __syncthreads();
    }

    // ---- epilogue: dump accums to smem, then LSTM cell per (batch, unit) ----
    __syncthreads();
#pragma unroll
    for (int mb = 0; mb < 2; mb++)
#pragma unroll
        for (int nb = 0; nb < 8; nb++) {
            int r0 = wm * 32 + mb * 16 + grp;
            int cc = wn * 64 + nb * 8 + 2 * tig;
            sm[r0 * 128 + cc] = acc[mb][nb][0];
            sm[r0 * 128 + cc + 1] = acc[mb][nb][1];
            sm[(r0 + 8) * 128 + cc] = acc[mb][nb][2];
            sm[(r0 + 8) * 128 + cc + 1] = acc[mb][nb][3];
        }
    __syncthreads();

    for (int q = tid; q < 128 * 32; q += 256) {
        int mi = q >> 5, uo = q & 31;
        int b = m0 + mi;
        int u = u0 + uo;
        float gi = sm[mi * 128 + uo] + bias[u];
        float gf = sm[mi * 128 + 32 + uo] + bias[1024 + u];
        float gg = sm[mi * 128 + 64 + uo] + bias[2048 + u];
        float go = sm[mi * 128 + 96 + uo] + bias[3072 + u];
        float cp = cbuf[(size_t)b * HH + u];
        float cn = sigmoidf_(gf) * cp + sigmoidf_(gi) * tanhf(gg);
        float hn = sigmoidf_(go) * tanhf(cn);
        float hn_r = rna_tf32(hn);
        bool upd = !masked || (t < lengths[b] - 1);
        if (upd) {
            cbuf[(size_t)b * HH + u] = cn;
            h_write[(size_t)b * HH + u] = hn_r;
        } else {
            h_write[(size_t)b * HH + u] = h_read[(size_t)b * HH + u];
        }
        if (hn_out) hn_out[(size_t)b * HH + u] = hn_r;
    }
}

// ---------------------------------------------------------------------------
// Decoder linear readout: fb2 = fb + h1 @ W_lin.T + b_lin ; out = fb2*std+mean
// One block per batch row; warp-per-output dot products.
// ---------------------------------------------------------------------------
__global__ void linear_kernel(const float* __restrict__ h1, const float* __restrict__ Wlin,
                              const float* __restrict__ blin, const float* __restrict__ mean,
                              const float* __restrict__ stdv, float* __restrict__ fb,
                              float* __restrict__ fbt, float* __restrict__ out, int step) {
    __shared__ float hs[HH];
    int b = blockIdx.x;
    int tid = threadIdx.x;
    for (int k = tid; k < HH; k += 256) hs[k] = h1[(size_t)b * HH + k];
    __syncthreads();
    int w = tid >> 5, lane = tid & 31;
#pragma unroll
    for (int j = 0; j < 9; j++) {
        int n = w + 8 * j;   // covers 0..71 exactly
        float s = 0.0f;
        for (int k = lane; k < HH; k += 32) s += hs[k] * Wlin[(size_t)n * HH + k];
#pragma unroll
        for (int off = 16; off; off >>= 1) s += __shfl_xor_sync(0xffffffffu, s, off);
        if (lane == 0) {
            float f2 = fb[b * FF + n] + s + blin[n];
            fb[b * FF + n] = f2;
            fbt[b * FP + n] = rna_tf32(f2);
            out[((size_t)step * BB + b) * FF + n] = f2 * stdv[n] + mean[n];
        }
    }
}

// ---------------------------------------------------------------------------
// Host orchestration (graph-capturable: kernel launches + memsetAsync only)
// ---------------------------------------------------------------------------
extern "C" void kernel_launch(void* const* d_in, const int* in_sizes, int n_in,
                              void* d_out, int out_size) {
    int off = (n_in >= 15) ? 1 : 0;  // 'output_length' scalar may or may not be materialized
    const float* batch_u = (const float*)d_in[0];
    const int* lengths   = (const int*)d_in[1];
    const float* mean    = (const float*)d_in[2 + off];
    const float* stdv    = (const float*)d_in[3 + off];
    const float* Wih0    = (const float*)d_in[4 + off];
    const float* Whh0    = (const float*)d_in[5 + off];
    const float* bih0    = (const float*)d_in[6 + off];
    const float* bhh0    = (const float*)d_in[7 + off];
    const float* Wih1    = (const float*)d_in[8 + off];
    const float* Whh1    = (const float*)d_in[9 + off];
    const float* bih1    = (const float*)d_in[10 + off];
    const float* bhh1    = (const float*)d_in[11 + off];
    const float* Wlin    = (const float*)d_in[12 + off];
    const float* blin    = (const float*)d_in[13 + off];
    float* out = (float*)d_out;
    const int OUTL = out_size / (BB * FF);   // 32

    Scratch* S = nullptr;
    cudaGetSymbolAddress((void**)&S, g_scratch);

    // Opt-in dynamic smem (first call is pre-capture, so this takes effect there;
    // the in-capture repeat is an idempotent no-op).
    cudaFuncSetAttribute(lstm_gemm_kernel, cudaFuncAttributeMaxDynamicSharedMemorySize,
                         SMEM_BYTES);

    // --- per-replay state init ---
    cudaMemsetAsync(S->h0[0], 0, sizeof(float) * BB * HH);
    cudaMemsetAsync(S->h1[0], 0, sizeof(float) * BB * HH);
    cudaMemsetAsync(S->c0, 0, sizeof(float) * BB * HH);
    cudaMemsetAsync(S->c1, 0, sizeof(float) * BB * HH);
    cudaMemsetAsync(S->fbt, 0, sizeof(float) * BB * FP);

    // --- setup: normalize + TF32-round inputs and weights ---
    norm_kernel<<<(TT * BB * FP + 255) / 256, 256>>>(batch_u, mean, stdv, S->xnf, S->xg);
    conv_kernel<<<(G4 * HH + 255) / 256, 256>>>(Whh0, S->Whh0c, G4 * HH);
    conv_kernel<<<(G4 * HH + 255) / 256, 256>>>(Wih1, S->Wih1c, G4 * HH);
    conv_kernel<<<(G4 * HH + 255) / 256, 256>>>(Whh1, S->Whh1c, G4 * HH);
    pad_kernel<<<(G4 * FP + 255) / 256, 256>>>(Wih0, S->Wih0p);
    bias_kernel<<<(G4 + 255) / 256, 256>>>(bih0, bhh0, bih1, bhh1, S->bias0, S->bias1);

    dim3 grid(BB / 128, HH / 32);   // 4 x 32 = 128 CTAs
    int cur = 0;

    // --- encoder: 63 masked steps ---
    for (int t = 0; t < TT - 1; t++) {
        lstm_gemm_kernel<<<grid, 256, SMEM_BYTES>>>(
            S->xg + (size_t)t * BB * FP, FP, S->Wih0p, FP, FP,
            S->h0[cur], S->Whh0c, HH, S->bias0,
            S->h0[cur], S->h0[cur ^ 1], S->c0, S->h0n, lengths, t, 1);
        lstm_gemm_kernel<<<grid, 256, SMEM_BYTES>>>(
            S->h0n, HH, S->Wih1c, HH, HH,
            S->h1[cur], S->Whh1c, HH, S->bias1,
            S->h1[cur], S->h1[cur ^ 1], S->c1, nullptr, lengths, t, 1);
        cur ^= 1;
    }

    // --- feedback gather ---
    gather_kernel<<<BB, 128>>>(lengths, S->xnf, S->fb, S->fbt);

    // --- decoder: OUTL steps ---
    for (int d = 0; d < OUTL; d++) {
        lstm_gemm_kernel<<<grid, 256, SMEM_BYTES>>>(
            S->fbt, FP, S->Wih0p, FP, FP,
            S->h0[cur], S->Whh0c, HH, S->bias0,
            S->h0[cur], S->h0[cur ^ 1], S->c0, S->h0n, nullptr, 0, 0);
        lstm_gemm_kernel<<<grid, 256, SMEM_BYTES>>>(
            S->h0n, HH, S->Wih1c, HH, HH,
            S->h1[cur], S->Whh1c, HH, S->bias1,
            S->h1[cur], S->h1[cur ^ 1], S->c1, nullptr, nullptr, 0, 0);
        linear_kernel<<<BB, 256>>>(S->h1[cur ^ 1], Wlin, blin, mean, stdv,
                                   S->fb, S->fbt, out, d);
        cur ^= 1;
    }
}

// round 3
// speedup vs baseline: 2.0457x; 2.0457x over previous
#include <cuda_runtime.h>
#include <cuda_bf16.h>
#include <math.h>
#include <stdint.h>
#include <stddef.h>

#define TT 64
#define BB 512
#define FF 72
#define HH 1024
#define G4 4096
#define BLK 8192                 // elements per 128x64 bf16 tile (16KB)
#define NSTAGE 4
#define STAGE_BYTES 32768        // A tile 16KB + B tile 16KB
#define SMEM_BYTES (NSTAGE * STAGE_BYTES + 1024)

// ---------------------------------------------------------------------------
// Scratch (device globals; allocations are forbidden)
// ---------------------------------------------------------------------------
struct __align__(16) Scratch {
    float xnf[TT * BB * FF];                 // normalized input fp32 (for feedback gather)
    float bias0[G4], bias1[G4];
    float c0[BB * HH], c1[BB * HH];
    float h1f[BB * HH];                      // fresh fp32 h1 for decoder linear
    float fb[BB * FF];                       // feedback accumulator fp32
    __nv_bfloat16 xg[(TT - 1) * 4 * 2 * BLK];   // [t][m][2][BLK] swizzled
    __nv_bfloat16 W0[32 * 18 * BLK];         // [j][18][BLK] (Wih0 pad 2 + Whh0 16)
    __nv_bfloat16 W1[32 * 32 * BLK];         // [j][32][BLK] (Wih1 16 + Whh1 16)
    __nv_bfloat16 h0s[2][4 * 16 * BLK];      // ping-pong, [m][16][BLK] swizzled
    __nv_bfloat16 h1s[2][4 * 16 * BLK];
    __nv_bfloat16 h0n[4 * 16 * BLK];         // fresh layer0 output, swizzled
    __nv_bfloat16 fbt[4 * 2 * BLK];          // feedback, swizzled, padded
};
__device__ Scratch g_scratch;

// ---------------------------------------------------------------------------
// Helpers
// ---------------------------------------------------------------------------
__device__ __forceinline__ int swb(int byte) {        // SW128 swizzled byte offset
    return byte ^ ((byte >> 3) & 0x70);
}
__device__ __forceinline__ int swofs(int r, int k) {   // bf16 element index in SW128 tile
    return swb(r * 128 + k * 2) >> 1;
}
__device__ __forceinline__ float sigmoidf_(float x) { return 1.0f / (1.0f + expf(-x)); }
__device__ __forceinline__ void cp16(uint32_t saddr, const void* gaddr) {
    asm volatile("cp.async.cg.shared.global [%0], [%1], 16;\n" :: "r"(saddr), "l"(gaddr));
}
__device__ __forceinline__ uint32_t smem_u32(const void* p) {
    return (uint32_t)__cvta_generic_to_shared(p);
}
__device__ __forceinline__ void ldsm4(uint32_t* r, uint32_t addr) {
    asm volatile("ldmatrix.sync.aligned.m8n8.x4.shared.b16 {%0,%1,%2,%3}, [%4];"
                 : "=r"(r[0]), "=r"(r[1]), "=r"(r[2]), "=r"(r[3]) : "r"(addr));
}
__device__ __forceinline__ void mma_bf16(float* c, const uint32_t* a, const uint32_t* b) {
    asm volatile(
        "mma.sync.aligned.m16n8k16.row.col.f32.bf16.bf16.f32 "
        "{%0,%1,%2,%3},{%4,%5,%6,%7},{%8,%9},{%0,%1,%2,%3};\n"
        : "+f"(c[0]), "+f"(c[1]), "+f"(c[2]), "+f"(c[3])
        : "r"(a[0]), "r"(a[1]), "r"(a[2]), "r"(a[3]), "r"(b[0]), "r"(b[1]));
}

// ---------------------------------------------------------------------------
// Setup kernels
// ---------------------------------------------------------------------------
__global__ void norm_f_kernel(const float* __restrict__ u, const float* __restrict__ mean,
                              const float* __restrict__ stdv, float* __restrict__ xnf) {
    int idx = blockIdx.x * blockDim.x + threadIdx.x;
    if (idx >= TT * BB * FF) return;
    int j = idx % FF;
    xnf[idx] = (u[idx] - mean[j]) / stdv[j];
}

__global__ void xg_swz_kernel(const float* __restrict__ xnf, __nv_bfloat16* __restrict__ dst) {
    int idx = blockIdx.x * blockDim.x + threadIdx.x;
    if (idx >= (TT - 1) * 4 * 2 * BLK) return;
    int e = idx & (BLK - 1);
    int i = (idx >> 13) & 1;
    int m = (idx >> 14) & 3;
    int t = idx >> 16;
    int r = e >> 6, k = e & 63;
    int b = m * 128 + r;
    int col = i * 64 + k;
    float v = (col < FF) ? xnf[((size_t)t * BB + b) * FF + col] : 0.0f;
    dst[(size_t)(idx >> 13) * BLK + swofs(r, k)] = __float2bfloat16(v);
}

__global__ void wsw_kernel(__nv_bfloat16* __restrict__ dst, const float* __restrict__ Wih,
                           int cIh, int srcCols, const float* __restrict__ Whh, int Ct) {
    int idx = blockIdx.x * blockDim.x + threadIdx.x;
    if (idx >= 32 * Ct * BLK) return;
    int e = idx & (BLK - 1);
    int blk = idx >> 13;           // j*Ct + i
    int i = blk % Ct;
    int j = blk / Ct;
    int r = e >> 6, k = e & 63;
    int n = ((r >> 5) << 10) + j * 32 + (r & 31);
    float v;
    if (i < cIh) {
        int col = i * 64 + k;
        v = (col < srcCols) ? Wih[(size_t)n * srcCols + col] : 0.0f;
    } else {
        int col = (i - cIh) * 64 + k;
        v = Whh[(size_t)n * HH + col];
    }
    dst[(size_t)blk * BLK + swofs(r, k)] = __float2bfloat16(v);
}

__global__ void bias_kernel(const float* bi0, const float* bh0, const float* bi1,
                            const float* bh1, float* b0, float* b1) {
    int idx = blockIdx.x * blockDim.x + threadIdx.x;
    if (idx < G4) {
        b0[idx] = bi0[idx] + bh0[idx];
        b1[idx] = bi1[idx] + bh1[idx];
    }
}

__global__ void gather_kernel(const int* __restrict__ lengths, const float* __restrict__ xnf,
                              float* __restrict__ fb, __nv_bfloat16* __restrict__ fbt) {
    int b = blockIdx.x, j = threadIdx.x;   // j in [0,128)
    if (j >= 128) return;
    int tt = lengths[b] - 1;
    float v = (j < FF) ? xnf[((size_t)tt * BB + b) * FF + j] : 0.0f;
    if (j < FF) fb[b * FF + j] = v;
    fbt[(size_t)((b >> 7) * 2 + (j >> 6)) * BLK + swofs(b & 127, j & 63)] = __float2bfloat16(v);
}

// ---------------------------------------------------------------------------
// Fused bf16 HMMA GEMM + LSTM epilogue.
// gates[m][n] = bias[n] + [A0;A1] @ W over concatenated K.
// CTA tile: 128 batch x (4 gates x 32 units). 8 warps = 4 M x 2 N.
// All operands pre-swizzled SW128 16KB tiles in gmem; one bulk cp.async per tile.
// ---------------------------------------------------------------------------
__global__ void __launch_bounds__(256) lstm_mma_kernel(
    const __nv_bfloat16* __restrict__ A0, int C0,
    const __nv_bfloat16* __restrict__ A1, int C1,
    const __nv_bfloat16* __restrict__ W,
    const float* __restrict__ bias,
    const __nv_bfloat16* __restrict__ h_read, __nv_bfloat16* __restrict__ h_write,
    float* __restrict__ cbuf,
    __nv_bfloat16* __restrict__ hn_sw, float* __restrict__ hn_f32,
    const int* __restrict__ lengths, int t, int masked) {
    extern __shared__ char raw_sm[];
    char* dsm = (char*)(((uintptr_t)raw_sm + 1023) & ~(uintptr_t)1023);
    const uint32_t dsm32 = smem_u32(dsm);

    const int tid = threadIdx.x;
    const int w = tid >> 5, lane = tid & 31;
    const int wm = w & 3, wn = w >> 2;     // 4 M-warps x 2 N-warps
    const int C = C0 + C1;
    const int m0 = blockIdx.x * 128;
    const int u0 = blockIdx.y * 32;
    const __nv_bfloat16* A0m = A0 + (size_t)blockIdx.x * C0 * BLK;
    const __nv_bfloat16* A1m = A1 + (size_t)blockIdx.x * C1 * BLK;
    const __nv_bfloat16* Wm = W + (size_t)blockIdx.y * C * BLK;

    // per-lane ldmatrix source patterns (tile-relative, before swizzle)
    const int rowA = wm * 32 + (lane & 15);            // + mtile*16
    const int cbA = (lane >> 4) * 16;                  // + ks*32
    const int rowB = wn * 64 + (lane & 7) + ((lane >> 4) & 1) * 8;   // + pair*16
    const int cbB = ((lane >> 3) & 1) * 16;            // + ks*32

    float acc[2][8][4];
#pragma unroll
    for (int a = 0; a < 2; a++)
#pragma unroll
        for (int b = 0; b < 8; b++)
#pragma unroll
            for (int c = 0; c < 4; c++) acc[a][b][c] = 0.0f;

    auto issue_chunk = [&](int j, int s) {
        const char* asrc = (const char*)((j < C0) ? (A0m + (size_t)j * BLK)
                                                  : (A1m + (size_t)(j - C0) * BLK));
        const char* bsrc = (const char*)(Wm + (size_t)j * BLK);
        uint32_t da = dsm32 + s * STAGE_BYTES + tid * 16;
#pragma unroll
        for (int r = 0; r < 4; r++) cp16(da + r * 4096, asrc + tid * 16 + r * 4096);
        uint32_t db = da + 16384;
#pragma unroll
        for (int r = 0; r < 4; r++) cp16(db + r * 4096, bsrc + tid * 16 + r * 4096);
        asm volatile("cp.async.commit_group;\n" ::);
    };

#pragma unroll
    for (int j = 0; j < NSTAGE - 1; j++) issue_chunk(j, j);

    for (int i = 0; i < C; i++) {
        const int s = i & (NSTAGE - 1);
        asm volatile("cp.async.wait_group %0;\n" :: "n"(NSTAGE - 2));
        __syncthreads();
        const int j = i + NSTAGE - 1;
        if (j < C) issue_chunk(j, j & (NSTAGE - 1));

        const uint32_t Ab = dsm32 + s * STAGE_BYTES;
        const uint32_t Bb = Ab + 16384;
#pragma unroll
        for (int ks = 0; ks < 4; ks++) {
            uint32_t afr[2][4];
#pragma unroll
            for (int mt = 0; mt < 2; mt++)
                ldsm4(afr[mt], Ab + swb((rowA + mt * 16) * 128 + ks * 32 + cbA));
            uint32_t bfr[8][2];
#pragma unroll
            for (int pr = 0; pr < 4; pr++) {
                uint32_t r4[4];
                ldsm4(r4, Bb + swb((rowB + pr * 16) * 128 + ks * 32 + cbB));
                bfr[2 * pr][0] = r4[0]; bfr[2 * pr][1] = r4[1];
                bfr[2 * pr + 1][0] = r4[2]; bfr[2 * pr + 1][1] = r4[3];
            }
#pragma unroll
            for (int mt = 0; mt < 2; mt++)
#pragma unroll
                for (int nt = 0; nt < 8; nt++) mma_bf16(acc[mt][nt], afr[mt], bfr[nt]);
        }
    }

    // ---- epilogue: regs -> smem -> LSTM cell ----
    __syncthreads();   // all compute done; reuse stage smem as fp32 [128][129]
    float* smf = (float*)dsm;
    {
        const int rg = lane >> 2, cg = (lane & 3) * 2;
#pragma unroll
        for (int mt = 0; mt < 2; mt++)
#pragma unroll
            for (int nt = 0; nt < 8; nt++) {
                int r0 = wm * 32 + mt * 16 + rg;
                int cc = wn * 64 + nt * 8 + cg;
                smf[r0 * 129 + cc] = acc[mt][nt][0];
                smf[r0 * 129 + cc + 1] = acc[mt][nt][1];
                smf[(r0 + 8) * 129 + cc] = acc[mt][nt][2];
                smf[(r0 + 8) * 129 + cc + 1] = acc[mt][nt][3];
            }
    }
    __syncthreads();

    for (int q = tid; q < 128 * 32; q += 256) {
        int mi = q >> 5, uo = q & 31;
        int b = m0 + mi;
        int u = u0 + uo;
        float gi = smf[mi * 129 + uo] + bias[u];
        float gf = smf[mi * 129 + 32 + uo] + bias[1024 + u];
        float gg = smf[mi * 129 + 64 + uo] + bias[2048 + u];
        float go = smf[mi * 129 + 96 + uo] + bias[3072 + u];
        float cp = cbuf[(size_t)b * HH + u];
        float cn = sigmoidf_(gf) * cp + sigmoidf_(gi) * tanhf(gg);
        float hn = sigmoidf_(go) * tanhf(cn);
        __nv_bfloat16 hb = __float2bfloat16(hn);
        size_t hidx = (size_t)((b >> 7) * 16 + (u >> 6)) * BLK + swofs(b & 127, u & 63);
        bool upd = !masked || (t < lengths[b] - 1);
        if (upd) {
            cbuf[(size_t)b * HH + u] = cn;
            h_write[hidx] = hb;
        } else {
            h_write[hidx] = h_read[hidx];
        }
        if (hn_sw) hn_sw[hidx] = hb;
        if (hn_f32) hn_f32[(size_t)b * HH + u] = hn;
    }
}

// ---------------------------------------------------------------------------
// Decoder linear readout: fb2 = fb + h1 @ W_lin.T + b_lin ; out = fb2*std+mean
// ---------------------------------------------------------------------------
__global__ void linear_kernel(const float* __restrict__ h1, const float* __restrict__ Wlin,
                              const float* __restrict__ blin, const float* __restrict__ mean,
                              const float* __restrict__ stdv, float* __restrict__ fb,
                              __nv_bfloat16* __restrict__ fbt, float* __restrict__ out,
                              int step) {
    __shared__ float hs[HH];
    int b = blockIdx.x;
    int tid = threadIdx.x;
    for (int k = tid; k < HH; k += 256) hs[k] = h1[(size_t)b * HH + k];
    __syncthreads();
    int w = tid >> 5, lane = tid & 31;
#pragma unroll
    for (int j = 0; j < 9; j++) {
        int n = w + 8 * j;   // 0..71
        float s = 0.0f;
        for (int k = lane; k < HH; k += 32) s += hs[k] * Wlin[(size_t)n * HH + k];
#pragma unroll
        for (int off = 16; off; off >>= 1) s += __shfl_xor_sync(0xffffffffu, s, off);
        if (lane == 0) {
            float f2 = fb[b * FF + n] + s + blin[n];
            fb[b * FF + n] = f2;
            fbt[(size_t)((b >> 7) * 2 + (n >> 6)) * BLK + swofs(b & 127, n & 63)] =
                __float2bfloat16(f2);
            out[((size_t)step * BB + b) * FF + n] = f2 * stdv[n] + mean[n];
        }
    }
}

// ---------------------------------------------------------------------------
// Host orchestration
// ---------------------------------------------------------------------------
extern "C" void kernel_launch(void* const* d_in, const int* in_sizes, int n_in,
                              void* d_out, int out_size) {
    int off = (n_in >= 15) ? 1 : 0;
    const float* batch_u = (const float*)d_in[0];
    const int* lengths   = (const int*)d_in[1];
    const float* mean    = (const float*)d_in[2 + off];
    const float* stdv    = (const float*)d_in[3 + off];
    const float* Wih0    = (const float*)d_in[4 + off];
    const float* Whh0    = (const float*)d_in[5 + off];
    const float* bih0    = (const float*)d_in[6 + off];
    const float* bhh0    = (const float*)d_in[7 + off];
    const float* Wih1    = (const float*)d_in[8 + off];
    const float* Whh1    = (const float*)d_in[9 + off];
    const float* bih1    = (const float*)d_in[10 + off];
    const float* bhh1    = (const float*)d_in[11 + off];
    const float* Wlin    = (const float*)d_in[12 + off];
    const float* blin    = (const float*)d_in[13 + off];
    float* out = (float*)d_out;
    const int OUTL = out_size / (BB * FF);

    Scratch* S = nullptr;
    cudaGetSymbolAddress((void**)&S, g_scratch);
    cudaFuncSetAttribute(lstm_mma_kernel, cudaFuncAttributeMaxDynamicSharedMemorySize,
                         SMEM_BYTES);

    // per-replay state init
    cudaMemsetAsync(S->h0s[0], 0, sizeof(__nv_bfloat16) * 4 * 16 * BLK);
    cudaMemsetAsync(S->h1s[0], 0, sizeof(__nv_bfloat16) * 4 * 16 * BLK);
    cudaMemsetAsync(S->c0, 0, sizeof(float) * BB * HH);
    cudaMemsetAsync(S->c1, 0, sizeof(float) * BB * HH);

    // setup: normalize + pre-swizzle to bf16 SW128 tiles
    norm_f_kernel<<<(TT * BB * FF + 255) / 256, 256>>>(batch_u, mean, stdv, S->xnf);
    xg_swz_kernel<<<((TT - 1) * 4 * 2 * BLK + 255) / 256, 256>>>(S->xnf, S->xg);
    wsw_kernel<<<(32 * 18 * BLK + 255) / 256, 256>>>(S->W0, Wih0, 2, FF, Whh0, 18);
    wsw_kernel<<<(32 * 32 * BLK + 255) / 256, 256>>>(S->W1, Wih1, 16, HH, Whh1, 32);
    bias_kernel<<<(G4 + 255) / 256, 256>>>(bih0, bhh0, bih1, bhh1, S->bias0, S->bias1);

    dim3 grid(4, 32);
    int cur = 0;

    // encoder: 63 masked steps
    for (int t = 0; t < TT - 1; t++) {
        lstm_mma_kernel<<<grid, 256, SMEM_BYTES>>>(
            S->xg + (size_t)t * 8 * BLK, 2, S->h0s[cur], 16, S->W0, S->bias0,
            S->h0s[cur], S->h0s[cur ^ 1], S->c0, S->h0n, nullptr, lengths, t, 1);
        lstm_mma_kernel<<<grid, 256, SMEM_BYTES>>>(
            S->h0n, 16, S->h1s[cur], 16, S->W1, S->bias1,
            S->h1s[cur], S->h1s[cur ^ 1], S->c1, nullptr, nullptr, lengths, t, 1);
        cur ^= 1;
    }

    gather_kernel<<<BB, 128>>>(lengths, S->xnf, S->fb, S->fbt);

    // decoder
    for (int d = 0; d < OUTL; d++) {
        lstm_mma_kernel<<<grid, 256, SMEM_BYTES>>>(
            S->fbt, 2, S->h0s[cur], 16, S->W0, S->bias0,
            S->h0s[cur], S->h0s[cur ^ 1], S->c0, S->h0n, nullptr, nullptr, 0, 0);
        lstm_mma_kernel<<<grid, 256, SMEM_BYTES>>>(
            S->h0n, 16, S->h1s[cur], 16, S->W1, S->bias1,
            S->h1s[cur], S->h1s[cur ^ 1], S->c1, nullptr, S->h1f, nullptr, 0, 0);
        linear_kernel<<<BB, 256>>>(S->h1f, Wlin, blin, mean, stdv, S->fb, S->fbt, out, d);
        cur ^= 1;
    }
}